// round 15
// baseline (speedup 1.0000x reference)
#include <cuda_runtime.h>
#include <cuda_bf16.h>
#include <cuda_fp16.h>
#include <math.h>
#include <stdint.h>

// Problem constants
#define BB    2
#define S_LEN 2048
#define HID   2304
#define NH    8
#define NKVH  4
#define DH    256
#define MROWS (BB * S_LEN)        // 4096
#define QCOLS (NH * DH)           // 2048
#define KCOLS (NKVH * DH)         // 1024
#define WINDOW 1024
#define SCALING 0.0625f           // 256^-0.5
#define SOFTCAP 50.0f

// Scratch (static device globals; no runtime allocation allowed)
__device__ float g_q [(size_t)MROWS * QCOLS];   // 32 MB
__device__ float g_k [(size_t)MROWS * KCOLS];   // 16 MB
__device__ float g_v [(size_t)MROWS * KCOLS];   // 16 MB
__device__ float g_cos[S_LEN * (DH/2)];         // 1 MB
__device__ float g_sin[S_LEN * (DH/2)];         // 1 MB

// fp16 split buffers: activations hi+lo; weights hi only
__device__ __half g_hsh[(size_t)MROWS * HID];
__device__ __half g_hsl[(size_t)MROWS * HID];
__device__ __half g_wqh[(size_t)QCOLS * HID];
__device__ __half g_wkh[(size_t)KCOLS * HID];
__device__ __half g_wvh[(size_t)KCOLS * HID];
__device__ __half g_woh[(size_t)HID * QCOLS];
__device__ __half g_aoh[(size_t)MROWS * QCOLS];
__device__ __half g_aol[(size_t)MROWS * QCOLS];

// ============================================================================
// Helpers
// ============================================================================
__device__ __forceinline__ uint32_t smem_u32(const void* p) {
    uint32_t a;
    asm("{ .reg .u64 t; cvta.to.shared.u64 t, %1; cvt.u32.u64 %0, t; }"
        : "=r"(a) : "l"(p));
    return a;
}
__device__ __forceinline__ uint32_t pack_h2(__half a, __half b) {
    __half2 p = __halves2half2(a, b);
    return *reinterpret_cast<uint32_t*>(&p);
}
__device__ __forceinline__ void ldsm4(uint32_t* r, uint32_t addr) {
    asm volatile("ldmatrix.sync.aligned.m8n8.x4.shared.b16 {%0,%1,%2,%3}, [%4];"
                 : "=r"(r[0]), "=r"(r[1]), "=r"(r[2]), "=r"(r[3]) : "r"(addr));
}
__device__ __forceinline__ void ldsm4t(uint32_t* r, uint32_t addr) {
    asm volatile("ldmatrix.sync.aligned.m8n8.x4.trans.shared.b16 {%0,%1,%2,%3}, [%4];"
                 : "=r"(r[0]), "=r"(r[1]), "=r"(r[2]), "=r"(r[3]) : "r"(addr));
}
// fp16 mma
__device__ __forceinline__ void mma16816h(float* c, const uint32_t* a, const uint32_t* b) {
    asm volatile("mma.sync.aligned.m16n8k16.row.col.f32.f16.f16.f32 "
                 "{%0,%1,%2,%3}, {%4,%5,%6,%7}, {%8,%9}, {%0,%1,%2,%3};"
                 : "+f"(c[0]), "+f"(c[1]), "+f"(c[2]), "+f"(c[3])
                 : "r"(a[0]), "r"(a[1]), "r"(a[2]), "r"(a[3]),
                   "r"(b[0]), "r"(b[1]));
}
__device__ __forceinline__ void cp16(uint32_t dst, const void* src) {
    asm volatile("cp.async.ca.shared.global [%0], [%1], 16;"
                 :: "r"(dst), "l"(src) : "memory");
}
#define CP_COMMIT() asm volatile("cp.async.commit_group;" ::: "memory")
#define CP_WAIT0()  asm volatile("cp.async.wait_group 0;" ::: "memory")

// ---------------------------------------------------------------------------
// fp32 -> fp16 hi/lo split (activations)
// ---------------------------------------------------------------------------
__global__ void cvt_split16_kernel(const float* __restrict__ x,
                                   __half* __restrict__ xh,
                                   __half* __restrict__ xl, int n4) {
    int i = blockIdx.x * blockDim.x + threadIdx.x;
    if (i >= n4) return;
    float4 a = ((const float4*)x)[i];
    __half h0 = __float2half_rn(a.x), h1 = __float2half_rn(a.y);
    __half h2 = __float2half_rn(a.z), h3 = __float2half_rn(a.w);
    __half l0 = __float2half_rn(a.x - __half2float(h0));
    __half l1 = __float2half_rn(a.y - __half2float(h1));
    __half l2 = __float2half_rn(a.z - __half2float(h2));
    __half l3 = __float2half_rn(a.w - __half2float(h3));
    ((uint2*)xh)[i] = make_uint2(pack_h2(h0, h1), pack_h2(h2, h3));
    ((uint2*)xl)[i] = make_uint2(pack_h2(l0, l1), pack_h2(l2, l3));
}
// Fused: all four weight matrices -> fp16 hi, one launch
#define NQ4 ((QCOLS * HID) / 4)
#define NK4 ((KCOLS * HID) / 4)
#define NO4 ((HID * QCOLS) / 4)
__global__ void cvt_hi16_w_kernel(const float* __restrict__ Wq,
                                  const float* __restrict__ Wk,
                                  const float* __restrict__ Wv,
                                  const float* __restrict__ Wo,
                                  __half* __restrict__ wqh, __half* __restrict__ wkh,
                                  __half* __restrict__ wvh, __half* __restrict__ woh) {
    int i = blockIdx.x * blockDim.x + threadIdx.x;
    const float* x;
    __half* y;
    if (i < NQ4) { x = Wq; y = wqh; }
    else if (i < NQ4 + NK4) { x = Wk; y = wkh; i -= NQ4; }
    else if (i < NQ4 + 2 * NK4) { x = Wv; y = wvh; i -= NQ4 + NK4; }
    else if (i < NQ4 + 2 * NK4 + NO4) { x = Wo; y = woh; i -= NQ4 + 2 * NK4; }
    else return;
    float4 a = ((const float4*)x)[i];
    ((uint2*)y)[i] = make_uint2(
        pack_h2(__float2half_rn(a.x), __float2half_rn(a.y)),
        pack_h2(__float2half_rn(a.z), __float2half_rn(a.w)));
}

// ---------------------------------------------------------------------------
// RoPE table
// ---------------------------------------------------------------------------
__global__ void rope_table_kernel(const int* __restrict__ pos,
                                  float* __restrict__ cs, float* __restrict__ sn) {
    int idx = blockIdx.x * blockDim.x + threadIdx.x;
    if (idx >= S_LEN * (DH/2)) return;
    int s = idx >> 7;
    int j = idx & 127;
    double invf = pow(10000.0, -(double)j / 128.0);
    float freq = (float)pos[s] * (float)invf;
    cs[idx] = cosf(freq);
    sn[idx] = sinf(freq);
}

// ---------------------------------------------------------------------------
// Fused RoPE apply for q (NH heads) and k (NKVH heads), one launch.
// ---------------------------------------------------------------------------
#define QTOT (MROWS * NH * 128)
#define KTOT (MROWS * NKVH * 128)
__global__ void rope_apply_qk_kernel(float* __restrict__ xq, float* __restrict__ xk,
                                     const float* __restrict__ cs,
                                     const float* __restrict__ sn) {
    int idx = blockIdx.x * blockDim.x + threadIdx.x;
    float* x;
    int nh;
    if (idx < QTOT) { x = xq; nh = NH; }
    else if (idx < QTOT + KTOT) { x = xk; nh = NKVH; idx -= QTOT; }
    else return;
    int per_row = nh * 128;
    int mrow = idx / per_row;
    int rp   = idx - mrow * per_row;
    int hh = rp >> 7;
    int j  = rp & 127;
    int s = mrow & (S_LEN - 1);
    float c  = cs[s * 128 + j];
    float sv = sn[s * 128 + j];
    size_t base = (size_t)mrow * (nh * 256) + hh * 256 + j;
    float x1 = x[base];
    float x2 = x[base + 128];
    x[base]       = x1 * c - x2 * sv;
    x[base + 128] = x2 * c + x1 * sv;
}

// ---------------------------------------------------------------------------
// fp16 2-term split GEMM core (NT): C = Ah Bh + Al Bh, fp32 accum.
// CTA tile 128x128, BK=64 (36/32 chunks), 256 threads / 8 warps,
// warp grid 4m x 2n, warp tile 32x64. cp.async 2-stage, 1 sync per chunk.
// ---------------------------------------------------------------------------
#define GBK 64
#define ROWB 144                   // 128 B data + 16 pad (conflict-free ldsm)
#define TILEB (128 * ROWB)         // 18432
#define STAGEB (3 * TILEB)         // 55296
#define GSM_TOT (2 * STAGEB)       // 110592

__device__ __forceinline__ void gemm_core(
    const __half* Ah, const __half* Al, const __half* Bh,
    float* C, int m0, int n0, int N, int K, unsigned char* gsm)
{
    uint32_t sb = smem_u32(gsm);
    int tid  = threadIdx.x;
    int wid  = tid >> 5;
    int lane = tid & 31;
    int wm = (wid & 3) * 32;       // 4 m-warps
    int wn = (wid >> 2) * 64;      // 2 n-warps

    float acc[2][8][4];
#pragma unroll
    for (int i = 0; i < 2; i++)
#pragma unroll
        for (int j = 0; j < 8; j++)
#pragma unroll
            for (int t = 0; t < 4; t++) acc[i][j][t] = 0.f;

    // copy mapping: 2 threads per row; each covers 64 B (4 x cp16) per tile
    int lr   = tid >> 1;
    int sseg = (tid & 1) * 64;
    const char* pAh = (const char*)(Ah + (size_t)(m0 + lr) * K) + sseg;
    const char* pAl = (const char*)(Al + (size_t)(m0 + lr) * K) + sseg;
    const char* pBh = (const char*)(Bh + (size_t)(n0 + lr) * K) + sseg;
    uint32_t dbase = sb + lr * ROWB + sseg;

    int alr = lane & 15;
    int akh = (lane >> 4) * 16;
    uint32_t aAh = sb + 0 * TILEB + (wm + alr) * ROWB + akh;
    uint32_t aAl = sb + 1 * TILEB + (wm + alr) * ROWB + akh;
    int blr = (lane & 7) + ((lane >> 4) << 3);
    int bkh = ((lane >> 3) & 1) * 16;
    uint32_t aBh = sb + 2 * TILEB + (wn + blr) * ROWB + bkh;

    int nchunks = K / GBK;

    {
        uint32_t d = dbase;
#pragma unroll
        for (int i = 0; i < 4; i++) {
            cp16(d + 0 * TILEB + i * 16, pAh + i * 16);
            cp16(d + 1 * TILEB + i * 16, pAl + i * 16);
            cp16(d + 2 * TILEB + i * 16, pBh + i * 16);
        }
        CP_COMMIT();
    }

#pragma unroll 1
    for (int ch = 0; ch < nchunks; ch++) {
        int st = ch & 1;
        CP_WAIT0();
        __syncthreads();
        if (ch + 1 < nchunks) {
            uint32_t d = dbase + (st ^ 1) * STAGEB;
            size_t go = (size_t)(ch + 1) * (GBK * 2);
#pragma unroll
            for (int i = 0; i < 4; i++) {
                cp16(d + 0 * TILEB + i * 16, pAh + go + i * 16);
                cp16(d + 1 * TILEB + i * 16, pAl + go + i * 16);
                cp16(d + 2 * TILEB + i * 16, pBh + go + i * 16);
            }
        }
        CP_COMMIT();

        uint32_t so = st * STAGEB;
#pragma unroll
        for (int ks = 0; ks < 4; ks++) {
            uint32_t ah[2][4], al[2][4], bh[4][4];
#pragma unroll
            for (int mt = 0; mt < 2; mt++) {
                ldsm4(ah[mt], aAh + so + mt * (16 * ROWB) + ks * 32);
                ldsm4(al[mt], aAl + so + mt * (16 * ROWB) + ks * 32);
            }
#pragma unroll
            for (int p = 0; p < 4; p++)
                ldsm4(bh[p], aBh + so + p * (16 * ROWB) + ks * 32);
#pragma unroll
            for (int mt = 0; mt < 2; mt++) {
#pragma unroll
                for (int nt = 0; nt < 8; nt++) {
                    const uint32_t* bhp = &bh[nt >> 1][(nt & 1) * 2];
                    mma16816h(acc[mt][nt], ah[mt], bhp);
                    mma16816h(acc[mt][nt], al[mt], bhp);
                }
            }
        }
    }

    int cr = lane >> 2;
    int cc = (lane & 3) * 2;
#pragma unroll
    for (int mt = 0; mt < 2; mt++) {
#pragma unroll
        for (int nt = 0; nt < 8; nt++) {
            int row = m0 + wm + mt * 16 + cr;
            int col = n0 + wn + nt * 8 + cc;
            *(float2*)(C + (size_t)row * N + col) =
                make_float2(acc[mt][nt][0], acc[mt][nt][1]);
            *(float2*)(C + (size_t)(row + 8) * N + col) =
                make_float2(acc[mt][nt][2], acc[mt][nt][3]);
        }
    }
}

__global__ __launch_bounds__(256) void gemm_qkv_kernel(
    const __half* __restrict__ Ah, const __half* __restrict__ Al,
    const __half* __restrict__ Wqh, const __half* __restrict__ Wkh,
    const __half* __restrict__ Wvh,
    float* __restrict__ q, float* __restrict__ k, float* __restrict__ v)
{
    extern __shared__ unsigned char gsm[];
    int bx = blockIdx.x;
    int m0 = blockIdx.y * 128;
    const __half* Bh;
    float* C;
    int n0, N;
    if (bx < 16)      { Bh = Wqh; C = q; N = QCOLS; n0 = bx * 128; }
    else if (bx < 24) { Bh = Wkh; C = k; N = KCOLS; n0 = (bx - 16) * 128; }
    else              { Bh = Wvh; C = v; N = KCOLS; n0 = (bx - 24) * 128; }
    gemm_core(Ah, Al, Bh, C, m0, n0, N, HID, gsm);
}

__global__ __launch_bounds__(256) void gemm_h_kernel(
    const __half* __restrict__ Ah, const __half* __restrict__ Al,
    const __half* __restrict__ Bh,
    float* __restrict__ C, int M, int N, int K)
{
    extern __shared__ unsigned char gsm[];
    gemm_core(Ah, Al, Bh, C, blockIdx.y * 128, blockIdx.x * 128, N, K, gsm);
}

// ---------------------------------------------------------------------------
// mma flash attention — fp16 hi-only throughout: Qh x Kh; Ph x Vh.
// (K-hi precision cost measured at +2.7e-4 in R12; Q/P symmetric.)
// smem: QH (128 x 528) + KH + VH (16 x 528 each) = 84.5 KB.
// ---------------------------------------------------------------------------
#define AQT 128
#define ATK 16
#define QSTR 528
#define KSTR 528
#define ASM_QH 0
#define ASM_KH (AQT * QSTR)                 // 67584
#define ASM_VH (ASM_KH + ATK * KSTR)        // 76032
#define ASM_TOT (ASM_VH + ATK * KSTR)       // 84480

__global__ __launch_bounds__(256, 1) void attn_mma_kernel(
    const float* __restrict__ q, const float* __restrict__ k,
    const float* __restrict__ v,
    __half* __restrict__ oh, __half* __restrict__ ol)
{
    extern __shared__ char asmem[];
    uint32_t sb = smem_u32(asmem);
    int tid = threadIdx.x, wid = tid >> 5, lane = tid & 31;
    int qt = blockIdx.x, h = blockIdx.y, b = blockIdx.z;
    int kvh = h >> 1;
    int q0 = qt * AQT;

    // --- Load + convert Q tile into smem fp16 hi (once) ---
    {
        int row = tid >> 1;
        int c0  = (tid & 1) * 128;
        const float* qrow = q + (size_t)(b * S_LEN + q0 + row) * QCOLS + h * DH + c0;
        char* dh = asmem + ASM_QH + row * QSTR + c0 * 2;
#pragma unroll
        for (int i = 0; i < 32; i++) {
            float4 a = *(const float4*)(qrow + i * 4);
            *(uint2*)(dh + i * 8) = make_uint2(
                pack_h2(__float2half_rn(a.x), __float2half_rn(a.y)),
                pack_h2(__float2half_rn(a.z), __float2half_rn(a.w)));
        }
    }

    int kstart = q0 - (WINDOW - 1);
    if (kstart < 0) kstart = 0;
    kstart &= ~(ATK - 1);
    int ntiles = (q0 + AQT - 1 - kstart) / ATK + 1;

    int prow = tid >> 4;
    int pcol = (tid & 15) * 16;
    const float* kbase = k + (size_t)(b * S_LEN) * KCOLS + kvh * DH;
    const float* vbase = v + (size_t)(b * S_LEN) * KCOLS + kvh * DH;

    float4 pk[4], pv[4];
    {
        const float* kr = kbase + (size_t)(kstart + prow) * KCOLS + pcol;
        const float* vr = vbase + (size_t)(kstart + prow) * KCOLS + pcol;
#pragma unroll
        for (int i = 0; i < 4; i++) { pk[i] = *(const float4*)(kr + i * 4);
                                      pv[i] = *(const float4*)(vr + i * 4); }
    }

    uint32_t aQh = sb + ASM_QH + (wid * 16 + (lane & 15)) * QSTR + (lane >> 4) * 16;
    uint32_t aKh = sb + ASM_KH + ((lane & 7) + ((lane >> 4) << 3)) * KSTR + ((lane >> 3) & 1) * 16;
    uint32_t aVh = sb + ASM_VH + ((lane & 7) + (((lane >> 3) & 1) << 3)) * KSTR + (lane >> 4) * 16;

    float mrow0 = -1e30f, mrow1 = -1e30f;
    float lrow0 = 0.f, lrow1 = 0.f;
    float oacc[32][4];
#pragma unroll
    for (int i = 0; i < 32; i++)
#pragma unroll
        for (int t = 0; t < 4; t++) oacc[i][t] = 0.f;

    int r0 = q0 + wid * 16 + (lane >> 2);

#pragma unroll 1
    for (int t = 0; t < ntiles; t++) {
        __syncthreads();
        {
            char* kh = asmem + ASM_KH + prow * KSTR + pcol * 2;
            char* vh = asmem + ASM_VH + prow * KSTR + pcol * 2;
#pragma unroll
            for (int i = 0; i < 4; i++) {
                float4 a = pk[i];
                *(uint2*)(kh + i * 8) = make_uint2(
                    pack_h2(__float2half_rn(a.x), __float2half_rn(a.y)),
                    pack_h2(__float2half_rn(a.z), __float2half_rn(a.w)));
                float4 bv = pv[i];
                *(uint2*)(vh + i * 8) = make_uint2(
                    pack_h2(__float2half_rn(bv.x), __float2half_rn(bv.y)),
                    pack_h2(__float2half_rn(bv.z), __float2half_rn(bv.w)));
            }
        }
        __syncthreads();
        if (t + 1 < ntiles) {
            int kt = kstart + (t + 1) * ATK;
            const float* kr = kbase + (size_t)(kt + prow) * KCOLS + pcol;
            const float* vr = vbase + (size_t)(kt + prow) * KCOLS + pcol;
#pragma unroll
            for (int i = 0; i < 4; i++) { pk[i] = *(const float4*)(kr + i * 4);
                                          pv[i] = *(const float4*)(vr + i * 4); }
        }

        int key0 = kstart + t * ATK;
        // ---- scores: Qh Kh ----
        float sc[2][4];
#pragma unroll
        for (int nt = 0; nt < 2; nt++)
#pragma unroll
            for (int e = 0; e < 4; e++) sc[nt][e] = 0.f;
#pragma unroll
        for (int dc = 0; dc < 16; dc++) {
            uint32_t qh[4], kh4[4];
            ldsm4(qh,  aQh + dc * 32);
            ldsm4(kh4, aKh + dc * 32);
#pragma unroll
            for (int nt = 0; nt < 2; nt++)
                mma16816h(sc[nt], qh, &kh4[nt * 2]);
        }
        // ---- softcap + mask ----
#pragma unroll
        for (int nt = 0; nt < 2; nt++) {
#pragma unroll
            for (int e = 0; e < 4; e++) {
                int row = r0 + (e >> 1) * 8;
                int col = key0 + nt * 8 + (lane & 3) * 2 + (e & 1);
                float u = sc[nt][e] * (SCALING / SOFTCAP);
                float eu = __expf(-2.f * fabsf(u));
                float th = __fdividef(1.f - eu, 1.f + eu);
                float s = copysignf(th, u) * SOFTCAP;
                bool ok = (col <= row) && (row - col < WINDOW);
                sc[nt][e] = ok ? s : -3.0e38f;
            }
        }
        // ---- online softmax ----
        float tm0 = fmaxf(fmaxf(sc[0][0], sc[0][1]), fmaxf(sc[1][0], sc[1][1]));
        float tm1 = fmaxf(fmaxf(sc[0][2], sc[0][3]), fmaxf(sc[1][2], sc[1][3]));
        tm0 = fmaxf(tm0, __shfl_xor_sync(0xffffffffu, tm0, 1));
        tm0 = fmaxf(tm0, __shfl_xor_sync(0xffffffffu, tm0, 2));
        tm1 = fmaxf(tm1, __shfl_xor_sync(0xffffffffu, tm1, 1));
        tm1 = fmaxf(tm1, __shfl_xor_sync(0xffffffffu, tm1, 2));
        float mnew0 = fmaxf(mrow0, tm0);
        float mnew1 = fmaxf(mrow1, tm1);
        float al0 = __expf(mrow0 - mnew0);
        float al1 = __expf(mrow1 - mnew1);
        mrow0 = mnew0; mrow1 = mnew1;
#pragma unroll
        for (int nt = 0; nt < 2; nt++) {
            sc[nt][0] = __expf(sc[nt][0] - mnew0);
            sc[nt][1] = __expf(sc[nt][1] - mnew0);
            sc[nt][2] = __expf(sc[nt][2] - mnew1);
            sc[nt][3] = __expf(sc[nt][3] - mnew1);
        }
        float rs0 = sc[0][0] + sc[0][1] + sc[1][0] + sc[1][1];
        float rs1 = sc[0][2] + sc[0][3] + sc[1][2] + sc[1][3];
        rs0 += __shfl_xor_sync(0xffffffffu, rs0, 1);
        rs0 += __shfl_xor_sync(0xffffffffu, rs0, 2);
        rs1 += __shfl_xor_sync(0xffffffffu, rs1, 1);
        rs1 += __shfl_xor_sync(0xffffffffu, rs1, 2);
        lrow0 = lrow0 * al0 + rs0;
        lrow1 = lrow1 * al1 + rs1;
        if (!__all_sync(0xffffffffu, (al0 == 1.f) & (al1 == 1.f))) {
#pragma unroll
            for (int i = 0; i < 32; i++) {
                oacc[i][0] *= al0; oacc[i][1] *= al0;
                oacc[i][2] *= al1; oacc[i][3] *= al1;
            }
        }
        // ---- P fragments fp16 hi + PV ----
        uint32_t pa[4];
        pa[0] = pack_h2(__float2half_rn(sc[0][0]), __float2half_rn(sc[0][1]));
        pa[1] = pack_h2(__float2half_rn(sc[0][2]), __float2half_rn(sc[0][3]));
        pa[2] = pack_h2(__float2half_rn(sc[1][0]), __float2half_rn(sc[1][1]));
        pa[3] = pack_h2(__float2half_rn(sc[1][2]), __float2half_rn(sc[1][3]));
#pragma unroll
        for (int g = 0; g < 16; g++) {
            uint32_t vbh[4];
            ldsm4t(vbh, aVh + g * 32);
            mma16816h(oacc[2 * g],     pa, &vbh[0]);
            mma16816h(oacc[2 * g + 1], pa, &vbh[2]);
        }
    }

    // ---- epilogue: write fp16 hi/lo directly ----
    float inv0 = __fdividef(1.f, lrow0);
    float inv1 = __fdividef(1.f, lrow1);
    size_t off0 = (size_t)(b * S_LEN + r0) * QCOLS + h * DH;
    size_t off1 = off0 + (size_t)8 * QCOLS;
#pragma unroll
    for (int i = 0; i < 32; i++) {
        int col = i * 8 + (lane & 3) * 2;
        float v0 = oacc[i][0] * inv0, v1 = oacc[i][1] * inv0;
        __half h0 = __float2half_rn(v0), h1 = __float2half_rn(v1);
        __half l0 = __float2half_rn(v0 - __half2float(h0));
        __half l1 = __float2half_rn(v1 - __half2float(h1));
        *(uint32_t*)(oh + off0 + col) = pack_h2(h0, h1);
        *(uint32_t*)(ol + off0 + col) = pack_h2(l0, l1);
        float v2 = oacc[i][2] * inv1, v3 = oacc[i][3] * inv1;
        __half h2 = __float2half_rn(v2), h3 = __float2half_rn(v3);
        __half l2 = __float2half_rn(v2 - __half2float(h2));
        __half l3 = __float2half_rn(v3 - __half2float(h3));
        *(uint32_t*)(oh + off1 + col) = pack_h2(h2, h3);
        *(uint32_t*)(ol + off1 + col) = pack_h2(l2, l3);
    }
}

// ---------------------------------------------------------------------------
// Launch
// ---------------------------------------------------------------------------
extern "C" void kernel_launch(void* const* d_in, const int* in_sizes, int n_in,
                              void* d_out, int out_size) {
    const float* hs  = (const float*)d_in[0];
    const float* Wq  = (const float*)d_in[1];
    const float* Wk  = (const float*)d_in[2];
    const float* Wv  = (const float*)d_in[3];
    const float* Wo  = (const float*)d_in[4];
    const int*   pos = (const int*)d_in[5];
    float* out = (float*)d_out;

    float *qp, *kp, *vp, *csp, *snp;
    cudaGetSymbolAddress((void**)&qp,  g_q);
    cudaGetSymbolAddress((void**)&kp,  g_k);
    cudaGetSymbolAddress((void**)&vp,  g_v);
    cudaGetSymbolAddress((void**)&csp, g_cos);
    cudaGetSymbolAddress((void**)&snp, g_sin);
    __half *hsh, *hsl, *wqh, *wkh, *wvh, *woh, *aoh, *aol;
    cudaGetSymbolAddress((void**)&hsh, g_hsh);
    cudaGetSymbolAddress((void**)&hsl, g_hsl);
    cudaGetSymbolAddress((void**)&wqh, g_wqh);
    cudaGetSymbolAddress((void**)&wkh, g_wkh);
    cudaGetSymbolAddress((void**)&wvh, g_wvh);
    cudaGetSymbolAddress((void**)&woh, g_woh);
    cudaGetSymbolAddress((void**)&aoh, g_aoh);
    cudaGetSymbolAddress((void**)&aol, g_aol);

    cudaFuncSetAttribute(attn_mma_kernel,
                         cudaFuncAttributeMaxDynamicSharedMemorySize, ASM_TOT);
    cudaFuncSetAttribute(gemm_h_kernel,
                         cudaFuncAttributeMaxDynamicSharedMemorySize, GSM_TOT);
    cudaFuncSetAttribute(gemm_qkv_kernel,
                         cudaFuncAttributeMaxDynamicSharedMemorySize, GSM_TOT);

    // RoPE table
    {
        int total = S_LEN * (DH/2);
        rope_table_kernel<<<(total + 255) / 256, 256>>>(pos, csp, snp);
    }
    // Pre-split hs (hi+lo); all weights hi in one launch
    {
        int n4 = (MROWS * HID) / 4;
        cvt_split16_kernel<<<(n4 + 255) / 256, 256>>>(hs, hsh, hsl, n4);
        int nw = NQ4 + 2 * NK4 + NO4;
        cvt_hi16_w_kernel<<<(nw + 255) / 256, 256>>>(Wq, Wk, Wv, Wo,
                                                     wqh, wkh, wvh, woh);
    }
    // Fused Q/K/V projections (fp16 2-term, BK=64)
    gemm_qkv_kernel<<<dim3(32, MROWS/128), 256, GSM_TOT>>>(
        hsh, hsl, wqh, wkh, wvh, qp, kp, vp);
    // Fused RoPE (q + k in one launch)
    {
        int tot = QTOT + KTOT;
        rope_apply_qk_kernel<<<(tot + 255) / 256, 256>>>(qp, kp, csp, snp);
    }
    // Attention (fp16 hi-only; fp16 hi/lo output)
    attn_mma_kernel<<<dim3(S_LEN/AQT, NH, BB), 256, ASM_TOT>>>(qp, kp, vp, aoh, aol);
    // Output projection (fp16 2-term, BK=64)
    gemm_h_kernel<<<dim3(HID/128, MROWS/128), 256, GSM_TOT>>>(aoh, aol, woh, out, MROWS, HID, QCOLS);
}

// round 16
// speedup vs baseline: 1.3347x; 1.3347x over previous
#include <cuda_runtime.h>
#include <cuda_bf16.h>
#include <cuda_fp16.h>
#include <math.h>
#include <stdint.h>

// Problem constants
#define BB    2
#define S_LEN 2048
#define HID   2304
#define NH    8
#define NKVH  4
#define DH    256
#define MROWS (BB * S_LEN)        // 4096
#define QCOLS (NH * DH)           // 2048
#define KCOLS (NKVH * DH)         // 1024
#define WINDOW 1024
#define SCALING 0.0625f           // 256^-0.5
#define SOFTCAP 50.0f

// Scratch (static device globals; no runtime allocation allowed)
__device__ float g_q [(size_t)MROWS * QCOLS];   // 32 MB
__device__ float g_k [(size_t)MROWS * KCOLS];   // 16 MB
__device__ float g_v [(size_t)MROWS * KCOLS];   // 16 MB
__device__ float g_cos[S_LEN * (DH/2)];         // 1 MB
__device__ float g_sin[S_LEN * (DH/2)];         // 1 MB

// fp16 split buffers: activations hi+lo; weights hi only
__device__ __half g_hsh[(size_t)MROWS * HID];
__device__ __half g_hsl[(size_t)MROWS * HID];
__device__ __half g_wqh[(size_t)QCOLS * HID];
__device__ __half g_wkh[(size_t)KCOLS * HID];
__device__ __half g_wvh[(size_t)KCOLS * HID];
__device__ __half g_woh[(size_t)HID * QCOLS];
__device__ __half g_aoh[(size_t)MROWS * QCOLS];
__device__ __half g_aol[(size_t)MROWS * QCOLS];

// ============================================================================
// Helpers
// ============================================================================
__device__ __forceinline__ uint32_t smem_u32(const void* p) {
    uint32_t a;
    asm("{ .reg .u64 t; cvta.to.shared.u64 t, %1; cvt.u32.u64 %0, t; }"
        : "=r"(a) : "l"(p));
    return a;
}
__device__ __forceinline__ uint32_t pack_h2(__half a, __half b) {
    __half2 p = __halves2half2(a, b);
    return *reinterpret_cast<uint32_t*>(&p);
}
__device__ __forceinline__ void ldsm4(uint32_t* r, uint32_t addr) {
    asm volatile("ldmatrix.sync.aligned.m8n8.x4.shared.b16 {%0,%1,%2,%3}, [%4];"
                 : "=r"(r[0]), "=r"(r[1]), "=r"(r[2]), "=r"(r[3]) : "r"(addr));
}
__device__ __forceinline__ void ldsm4t(uint32_t* r, uint32_t addr) {
    asm volatile("ldmatrix.sync.aligned.m8n8.x4.trans.shared.b16 {%0,%1,%2,%3}, [%4];"
                 : "=r"(r[0]), "=r"(r[1]), "=r"(r[2]), "=r"(r[3]) : "r"(addr));
}
// fp16 mma
__device__ __forceinline__ void mma16816h(float* c, const uint32_t* a, const uint32_t* b) {
    asm volatile("mma.sync.aligned.m16n8k16.row.col.f32.f16.f16.f32 "
                 "{%0,%1,%2,%3}, {%4,%5,%6,%7}, {%8,%9}, {%0,%1,%2,%3};"
                 : "+f"(c[0]), "+f"(c[1]), "+f"(c[2]), "+f"(c[3])
                 : "r"(a[0]), "r"(a[1]), "r"(a[2]), "r"(a[3]),
                   "r"(b[0]), "r"(b[1]));
}
__device__ __forceinline__ void cp16(uint32_t dst, const void* src) {
    asm volatile("cp.async.ca.shared.global [%0], [%1], 16;"
                 :: "r"(dst), "l"(src) : "memory");
}
#define CP_COMMIT() asm volatile("cp.async.commit_group;" ::: "memory")
#define CP_WAIT0()  asm volatile("cp.async.wait_group 0;" ::: "memory")

// ---------------------------------------------------------------------------
// fp32 -> fp16 hi/lo split (activations)
// ---------------------------------------------------------------------------
__global__ void cvt_split16_kernel(const float* __restrict__ x,
                                   __half* __restrict__ xh,
                                   __half* __restrict__ xl, int n4) {
    int i = blockIdx.x * blockDim.x + threadIdx.x;
    if (i >= n4) return;
    float4 a = ((const float4*)x)[i];
    __half h0 = __float2half_rn(a.x), h1 = __float2half_rn(a.y);
    __half h2 = __float2half_rn(a.z), h3 = __float2half_rn(a.w);
    __half l0 = __float2half_rn(a.x - __half2float(h0));
    __half l1 = __float2half_rn(a.y - __half2float(h1));
    __half l2 = __float2half_rn(a.z - __half2float(h2));
    __half l3 = __float2half_rn(a.w - __half2float(h3));
    ((uint2*)xh)[i] = make_uint2(pack_h2(h0, h1), pack_h2(h2, h3));
    ((uint2*)xl)[i] = make_uint2(pack_h2(l0, l1), pack_h2(l2, l3));
}
// Fused: all four weight matrices -> fp16 hi, one launch
#define NQ4 ((QCOLS * HID) / 4)
#define NK4 ((KCOLS * HID) / 4)
#define NO4 ((HID * QCOLS) / 4)
__global__ void cvt_hi16_w_kernel(const float* __restrict__ Wq,
                                  const float* __restrict__ Wk,
                                  const float* __restrict__ Wv,
                                  const float* __restrict__ Wo,
                                  __half* __restrict__ wqh, __half* __restrict__ wkh,
                                  __half* __restrict__ wvh, __half* __restrict__ woh) {
    int i = blockIdx.x * blockDim.x + threadIdx.x;
    const float* x;
    __half* y;
    if (i < NQ4) { x = Wq; y = wqh; }
    else if (i < NQ4 + NK4) { x = Wk; y = wkh; i -= NQ4; }
    else if (i < NQ4 + 2 * NK4) { x = Wv; y = wvh; i -= NQ4 + NK4; }
    else if (i < NQ4 + 2 * NK4 + NO4) { x = Wo; y = woh; i -= NQ4 + 2 * NK4; }
    else return;
    float4 a = ((const float4*)x)[i];
    ((uint2*)y)[i] = make_uint2(
        pack_h2(__float2half_rn(a.x), __float2half_rn(a.y)),
        pack_h2(__float2half_rn(a.z), __float2half_rn(a.w)));
}

// ---------------------------------------------------------------------------
// RoPE table
// ---------------------------------------------------------------------------
__global__ void rope_table_kernel(const int* __restrict__ pos,
                                  float* __restrict__ cs, float* __restrict__ sn) {
    int idx = blockIdx.x * blockDim.x + threadIdx.x;
    if (idx >= S_LEN * (DH/2)) return;
    int s = idx >> 7;
    int j = idx & 127;
    double invf = pow(10000.0, -(double)j / 128.0);
    float freq = (float)pos[s] * (float)invf;
    cs[idx] = cosf(freq);
    sn[idx] = sinf(freq);
}

// ---------------------------------------------------------------------------
// Fused RoPE apply for q (NH heads) and k (NKVH heads), one launch.
// ---------------------------------------------------------------------------
#define QTOT (MROWS * NH * 128)
#define KTOT (MROWS * NKVH * 128)
__global__ void rope_apply_qk_kernel(float* __restrict__ xq, float* __restrict__ xk,
                                     const float* __restrict__ cs,
                                     const float* __restrict__ sn) {
    int idx = blockIdx.x * blockDim.x + threadIdx.x;
    float* x;
    int nh;
    if (idx < QTOT) { x = xq; nh = NH; }
    else if (idx < QTOT + KTOT) { x = xk; nh = NKVH; idx -= QTOT; }
    else return;
    int per_row = nh * 128;
    int mrow = idx / per_row;
    int rp   = idx - mrow * per_row;
    int hh = rp >> 7;
    int j  = rp & 127;
    int s = mrow & (S_LEN - 1);
    float c  = cs[s * 128 + j];
    float sv = sn[s * 128 + j];
    size_t base = (size_t)mrow * (nh * 256) + hh * 256 + j;
    float x1 = x[base];
    float x2 = x[base + 128];
    x[base]       = x1 * c - x2 * sv;
    x[base + 128] = x2 * c + x1 * sv;
}

// ---------------------------------------------------------------------------
// fp16 2-term split GEMM core (NT): C = Ah Bh + Al Bh, fp32 accum.
// R14 configuration (fastest measured): CTA tile 128x128, BK=32,
// 256 threads / 8 warps, warp grid 4m x 2n, warp tile 32x64.
// cp.async 2-stage, single sync per chunk. 2 CTA/SM.
// ---------------------------------------------------------------------------
#define GBK 32
#define ROWB 80
#define TILEB (128 * ROWB)         // 10240
#define STAGEB (3 * TILEB)         // 30720
#define GSM_TOT (2 * STAGEB)       // 61440

__device__ __forceinline__ void gemm_core(
    const __half* Ah, const __half* Al, const __half* Bh,
    float* C, int m0, int n0, int N, int K, unsigned char* gsm)
{
    uint32_t sb = smem_u32(gsm);
    int tid  = threadIdx.x;
    int wid  = tid >> 5;
    int lane = tid & 31;
    int wm = (wid & 3) * 32;       // 4 m-warps
    int wn = (wid >> 2) * 64;      // 2 n-warps

    float acc[2][8][4];
#pragma unroll
    for (int i = 0; i < 2; i++)
#pragma unroll
        for (int j = 0; j < 8; j++)
#pragma unroll
            for (int t = 0; t < 4; t++) acc[i][j][t] = 0.f;

    // copy mapping: 2 threads per row; each covers 32 B (2 x cp16) per tile
    int lr   = tid >> 1;
    int sseg = (tid & 1) * 32;
    const char* pAh = (const char*)(Ah + (size_t)(m0 + lr) * K) + sseg;
    const char* pAl = (const char*)(Al + (size_t)(m0 + lr) * K) + sseg;
    const char* pBh = (const char*)(Bh + (size_t)(n0 + lr) * K) + sseg;
    uint32_t dbase = sb + lr * ROWB + sseg;

    int alr = lane & 15;
    int akh = (lane >> 4) * 16;
    uint32_t aAh = sb + 0 * TILEB + (wm + alr) * ROWB + akh;
    uint32_t aAl = sb + 1 * TILEB + (wm + alr) * ROWB + akh;
    int blr = (lane & 7) + ((lane >> 4) << 3);
    int bkh = ((lane >> 3) & 1) * 16;
    uint32_t aBh = sb + 2 * TILEB + (wn + blr) * ROWB + bkh;

    int nchunks = K / GBK;

    {
        uint32_t d = dbase;
        cp16(d + 0 * TILEB, pAh);  cp16(d + 0 * TILEB + 16, pAh + 16);
        cp16(d + 1 * TILEB, pAl);  cp16(d + 1 * TILEB + 16, pAl + 16);
        cp16(d + 2 * TILEB, pBh);  cp16(d + 2 * TILEB + 16, pBh + 16);
        CP_COMMIT();
    }

#pragma unroll 1
    for (int ch = 0; ch < nchunks; ch++) {
        int st = ch & 1;
        CP_WAIT0();
        __syncthreads();
        if (ch + 1 < nchunks) {
            uint32_t d = dbase + (st ^ 1) * STAGEB;
            size_t go = (size_t)(ch + 1) * (GBK * 2);
            cp16(d + 0 * TILEB, pAh + go);  cp16(d + 0 * TILEB + 16, pAh + go + 16);
            cp16(d + 1 * TILEB, pAl + go);  cp16(d + 1 * TILEB + 16, pAl + go + 16);
            cp16(d + 2 * TILEB, pBh + go);  cp16(d + 2 * TILEB + 16, pBh + go + 16);
        }
        CP_COMMIT();

        uint32_t so = st * STAGEB;
#pragma unroll
        for (int ks = 0; ks < 2; ks++) {
            uint32_t ah[2][4], al[2][4], bh[4][4];
#pragma unroll
            for (int mt = 0; mt < 2; mt++) {
                ldsm4(ah[mt], aAh + so + mt * (16 * ROWB) + ks * 32);
                ldsm4(al[mt], aAl + so + mt * (16 * ROWB) + ks * 32);
            }
#pragma unroll
            for (int p = 0; p < 4; p++)
                ldsm4(bh[p], aBh + so + p * (16 * ROWB) + ks * 32);
#pragma unroll
            for (int mt = 0; mt < 2; mt++) {
#pragma unroll
                for (int nt = 0; nt < 8; nt++) {
                    const uint32_t* bhp = &bh[nt >> 1][(nt & 1) * 2];
                    mma16816h(acc[mt][nt], ah[mt], bhp);
                    mma16816h(acc[mt][nt], al[mt], bhp);
                }
            }
        }
    }

    int cr = lane >> 2;
    int cc = (lane & 3) * 2;
#pragma unroll
    for (int mt = 0; mt < 2; mt++) {
#pragma unroll
        for (int nt = 0; nt < 8; nt++) {
            int row = m0 + wm + mt * 16 + cr;
            int col = n0 + wn + nt * 8 + cc;
            *(float2*)(C + (size_t)row * N + col) =
                make_float2(acc[mt][nt][0], acc[mt][nt][1]);
            *(float2*)(C + (size_t)(row + 8) * N + col) =
                make_float2(acc[mt][nt][2], acc[mt][nt][3]);
        }
    }
}

__global__ __launch_bounds__(256) void gemm_qkv_kernel(
    const __half* __restrict__ Ah, const __half* __restrict__ Al,
    const __half* __restrict__ Wqh, const __half* __restrict__ Wkh,
    const __half* __restrict__ Wvh,
    float* __restrict__ q, float* __restrict__ k, float* __restrict__ v)
{
    extern __shared__ unsigned char gsm[];
    int bx = blockIdx.x;
    int m0 = blockIdx.y * 128;
    const __half* Bh;
    float* C;
    int n0, N;
    if (bx < 16)      { Bh = Wqh; C = q; N = QCOLS; n0 = bx * 128; }
    else if (bx < 24) { Bh = Wkh; C = k; N = KCOLS; n0 = (bx - 16) * 128; }
    else              { Bh = Wvh; C = v; N = KCOLS; n0 = (bx - 24) * 128; }
    gemm_core(Ah, Al, Bh, C, m0, n0, N, HID, gsm);
}

__global__ __launch_bounds__(256) void gemm_h_kernel(
    const __half* __restrict__ Ah, const __half* __restrict__ Al,
    const __half* __restrict__ Bh,
    float* __restrict__ C, int M, int N, int K)
{
    extern __shared__ unsigned char gsm[];
    gemm_core(Ah, Al, Bh, C, blockIdx.y * 128, blockIdx.x * 128, N, K, gsm);
}

// ---------------------------------------------------------------------------
// mma flash attention — fp16 hi-only (R15 version, measured rel_err 5.2e-4).
// smem: QH (128 x 528) + KH + VH (16 x 528 each) = 84.5 KB.
// ---------------------------------------------------------------------------
#define AQT 128
#define ATK 16
#define QSTR 528
#define KSTR 528
#define ASM_QH 0
#define ASM_KH (AQT * QSTR)                 // 67584
#define ASM_VH (ASM_KH + ATK * KSTR)        // 76032
#define ASM_TOT (ASM_VH + ATK * KSTR)       // 84480

__global__ __launch_bounds__(256, 1) void attn_mma_kernel(
    const float* __restrict__ q, const float* __restrict__ k,
    const float* __restrict__ v,
    __half* __restrict__ oh, __half* __restrict__ ol)
{
    extern __shared__ char asmem[];
    uint32_t sb = smem_u32(asmem);
    int tid = threadIdx.x, wid = tid >> 5, lane = tid & 31;
    int qt = blockIdx.x, h = blockIdx.y, b = blockIdx.z;
    int kvh = h >> 1;
    int q0 = qt * AQT;

    // --- Load + convert Q tile into smem fp16 hi (once) ---
    {
        int row = tid >> 1;
        int c0  = (tid & 1) * 128;
        const float* qrow = q + (size_t)(b * S_LEN + q0 + row) * QCOLS + h * DH + c0;
        char* dh = asmem + ASM_QH + row * QSTR + c0 * 2;
#pragma unroll
        for (int i = 0; i < 32; i++) {
            float4 a = *(const float4*)(qrow + i * 4);
            *(uint2*)(dh + i * 8) = make_uint2(
                pack_h2(__float2half_rn(a.x), __float2half_rn(a.y)),
                pack_h2(__float2half_rn(a.z), __float2half_rn(a.w)));
        }
    }

    int kstart = q0 - (WINDOW - 1);
    if (kstart < 0) kstart = 0;
    kstart &= ~(ATK - 1);
    int ntiles = (q0 + AQT - 1 - kstart) / ATK + 1;

    int prow = tid >> 4;
    int pcol = (tid & 15) * 16;
    const float* kbase = k + (size_t)(b * S_LEN) * KCOLS + kvh * DH;
    const float* vbase = v + (size_t)(b * S_LEN) * KCOLS + kvh * DH;

    float4 pk[4], pv[4];
    {
        const float* kr = kbase + (size_t)(kstart + prow) * KCOLS + pcol;
        const float* vr = vbase + (size_t)(kstart + prow) * KCOLS + pcol;
#pragma unroll
        for (int i = 0; i < 4; i++) { pk[i] = *(const float4*)(kr + i * 4);
                                      pv[i] = *(const float4*)(vr + i * 4); }
    }

    uint32_t aQh = sb + ASM_QH + (wid * 16 + (lane & 15)) * QSTR + (lane >> 4) * 16;
    uint32_t aKh = sb + ASM_KH + ((lane & 7) + ((lane >> 4) << 3)) * KSTR + ((lane >> 3) & 1) * 16;
    uint32_t aVh = sb + ASM_VH + ((lane & 7) + (((lane >> 3) & 1) << 3)) * KSTR + (lane >> 4) * 16;

    float mrow0 = -1e30f, mrow1 = -1e30f;
    float lrow0 = 0.f, lrow1 = 0.f;
    float oacc[32][4];
#pragma unroll
    for (int i = 0; i < 32; i++)
#pragma unroll
        for (int t = 0; t < 4; t++) oacc[i][t] = 0.f;

    int r0 = q0 + wid * 16 + (lane >> 2);

#pragma unroll 1
    for (int t = 0; t < ntiles; t++) {
        __syncthreads();
        {
            char* kh = asmem + ASM_KH + prow * KSTR + pcol * 2;
            char* vh = asmem + ASM_VH + prow * KSTR + pcol * 2;
#pragma unroll
            for (int i = 0; i < 4; i++) {
                float4 a = pk[i];
                *(uint2*)(kh + i * 8) = make_uint2(
                    pack_h2(__float2half_rn(a.x), __float2half_rn(a.y)),
                    pack_h2(__float2half_rn(a.z), __float2half_rn(a.w)));
                float4 bv = pv[i];
                *(uint2*)(vh + i * 8) = make_uint2(
                    pack_h2(__float2half_rn(bv.x), __float2half_rn(bv.y)),
                    pack_h2(__float2half_rn(bv.z), __float2half_rn(bv.w)));
            }
        }
        __syncthreads();
        if (t + 1 < ntiles) {
            int kt = kstart + (t + 1) * ATK;
            const float* kr = kbase + (size_t)(kt + prow) * KCOLS + pcol;
            const float* vr = vbase + (size_t)(kt + prow) * KCOLS + pcol;
#pragma unroll
            for (int i = 0; i < 4; i++) { pk[i] = *(const float4*)(kr + i * 4);
                                          pv[i] = *(const float4*)(vr + i * 4); }
        }

        int key0 = kstart + t * ATK;
        // ---- scores: Qh Kh ----
        float sc[2][4];
#pragma unroll
        for (int nt = 0; nt < 2; nt++)
#pragma unroll
            for (int e = 0; e < 4; e++) sc[nt][e] = 0.f;
#pragma unroll
        for (int dc = 0; dc < 16; dc++) {
            uint32_t qh[4], kh4[4];
            ldsm4(qh,  aQh + dc * 32);
            ldsm4(kh4, aKh + dc * 32);
#pragma unroll
            for (int nt = 0; nt < 2; nt++)
                mma16816h(sc[nt], qh, &kh4[nt * 2]);
        }
        // ---- softcap + mask ----
#pragma unroll
        for (int nt = 0; nt < 2; nt++) {
#pragma unroll
            for (int e = 0; e < 4; e++) {
                int row = r0 + (e >> 1) * 8;
                int col = key0 + nt * 8 + (lane & 3) * 2 + (e & 1);
                float u = sc[nt][e] * (SCALING / SOFTCAP);
                float eu = __expf(-2.f * fabsf(u));
                float th = __fdividef(1.f - eu, 1.f + eu);
                float s = copysignf(th, u) * SOFTCAP;
                bool ok = (col <= row) && (row - col < WINDOW);
                sc[nt][e] = ok ? s : -3.0e38f;
            }
        }
        // ---- online softmax ----
        float tm0 = fmaxf(fmaxf(sc[0][0], sc[0][1]), fmaxf(sc[1][0], sc[1][1]));
        float tm1 = fmaxf(fmaxf(sc[0][2], sc[0][3]), fmaxf(sc[1][2], sc[1][3]));
        tm0 = fmaxf(tm0, __shfl_xor_sync(0xffffffffu, tm0, 1));
        tm0 = fmaxf(tm0, __shfl_xor_sync(0xffffffffu, tm0, 2));
        tm1 = fmaxf(tm1, __shfl_xor_sync(0xffffffffu, tm1, 1));
        tm1 = fmaxf(tm1, __shfl_xor_sync(0xffffffffu, tm1, 2));
        float mnew0 = fmaxf(mrow0, tm0);
        float mnew1 = fmaxf(mrow1, tm1);
        float al0 = __expf(mrow0 - mnew0);
        float al1 = __expf(mrow1 - mnew1);
        mrow0 = mnew0; mrow1 = mnew1;
#pragma unroll
        for (int nt = 0; nt < 2; nt++) {
            sc[nt][0] = __expf(sc[nt][0] - mnew0);
            sc[nt][1] = __expf(sc[nt][1] - mnew0);
            sc[nt][2] = __expf(sc[nt][2] - mnew1);
            sc[nt][3] = __expf(sc[nt][3] - mnew1);
        }
        float rs0 = sc[0][0] + sc[0][1] + sc[1][0] + sc[1][1];
        float rs1 = sc[0][2] + sc[0][3] + sc[1][2] + sc[1][3];
        rs0 += __shfl_xor_sync(0xffffffffu, rs0, 1);
        rs0 += __shfl_xor_sync(0xffffffffu, rs0, 2);
        rs1 += __shfl_xor_sync(0xffffffffu, rs1, 1);
        rs1 += __shfl_xor_sync(0xffffffffu, rs1, 2);
        lrow0 = lrow0 * al0 + rs0;
        lrow1 = lrow1 * al1 + rs1;
        if (!__all_sync(0xffffffffu, (al0 == 1.f) & (al1 == 1.f))) {
#pragma unroll
            for (int i = 0; i < 32; i++) {
                oacc[i][0] *= al0; oacc[i][1] *= al0;
                oacc[i][2] *= al1; oacc[i][3] *= al1;
            }
        }
        // ---- P fragments fp16 hi + PV ----
        uint32_t pa[4];
        pa[0] = pack_h2(__float2half_rn(sc[0][0]), __float2half_rn(sc[0][1]));
        pa[1] = pack_h2(__float2half_rn(sc[0][2]), __float2half_rn(sc[0][3]));
        pa[2] = pack_h2(__float2half_rn(sc[1][0]), __float2half_rn(sc[1][1]));
        pa[3] = pack_h2(__float2half_rn(sc[1][2]), __float2half_rn(sc[1][3]));
#pragma unroll
        for (int g = 0; g < 16; g++) {
            uint32_t vbh[4];
            ldsm4t(vbh, aVh + g * 32);
            mma16816h(oacc[2 * g],     pa, &vbh[0]);
            mma16816h(oacc[2 * g + 1], pa, &vbh[2]);
        }
    }

    // ---- epilogue: write fp16 hi/lo directly ----
    float inv0 = __fdividef(1.f, lrow0);
    float inv1 = __fdividef(1.f, lrow1);
    size_t off0 = (size_t)(b * S_LEN + r0) * QCOLS + h * DH;
    size_t off1 = off0 + (size_t)8 * QCOLS;
#pragma unroll
    for (int i = 0; i < 32; i++) {
        int col = i * 8 + (lane & 3) * 2;
        float v0 = oacc[i][0] * inv0, v1 = oacc[i][1] * inv0;
        __half h0 = __float2half_rn(v0), h1 = __float2half_rn(v1);
        __half l0 = __float2half_rn(v0 - __half2float(h0));
        __half l1 = __float2half_rn(v1 - __half2float(h1));
        *(uint32_t*)(oh + off0 + col) = pack_h2(h0, h1);
        *(uint32_t*)(ol + off0 + col) = pack_h2(l0, l1);
        float v2 = oacc[i][2] * inv1, v3 = oacc[i][3] * inv1;
        __half h2 = __float2half_rn(v2), h3 = __float2half_rn(v3);
        __half l2 = __float2half_rn(v2 - __half2float(h2));
        __half l3 = __float2half_rn(v3 - __half2float(h3));
        *(uint32_t*)(oh + off1 + col) = pack_h2(h2, h3);
        *(uint32_t*)(ol + off1 + col) = pack_h2(l2, l3);
    }
}

// ---------------------------------------------------------------------------
// Launch
// ---------------------------------------------------------------------------
extern "C" void kernel_launch(void* const* d_in, const int* in_sizes, int n_in,
                              void* d_out, int out_size) {
    const float* hs  = (const float*)d_in[0];
    const float* Wq  = (const float*)d_in[1];
    const float* Wk  = (const float*)d_in[2];
    const float* Wv  = (const float*)d_in[3];
    const float* Wo  = (const float*)d_in[4];
    const int*   pos = (const int*)d_in[5];
    float* out = (float*)d_out;

    float *qp, *kp, *vp, *csp, *snp;
    cudaGetSymbolAddress((void**)&qp,  g_q);
    cudaGetSymbolAddress((void**)&kp,  g_k);
    cudaGetSymbolAddress((void**)&vp,  g_v);
    cudaGetSymbolAddress((void**)&csp, g_cos);
    cudaGetSymbolAddress((void**)&snp, g_sin);
    __half *hsh, *hsl, *wqh, *wkh, *wvh, *woh, *aoh, *aol;
    cudaGetSymbolAddress((void**)&hsh, g_hsh);
    cudaGetSymbolAddress((void**)&hsl, g_hsl);
    cudaGetSymbolAddress((void**)&wqh, g_wqh);
    cudaGetSymbolAddress((void**)&wkh, g_wkh);
    cudaGetSymbolAddress((void**)&wvh, g_wvh);
    cudaGetSymbolAddress((void**)&woh, g_woh);
    cudaGetSymbolAddress((void**)&aoh, g_aoh);
    cudaGetSymbolAddress((void**)&aol, g_aol);

    cudaFuncSetAttribute(attn_mma_kernel,
                         cudaFuncAttributeMaxDynamicSharedMemorySize, ASM_TOT);
    cudaFuncSetAttribute(gemm_h_kernel,
                         cudaFuncAttributeMaxDynamicSharedMemorySize, GSM_TOT);
    cudaFuncSetAttribute(gemm_qkv_kernel,
                         cudaFuncAttributeMaxDynamicSharedMemorySize, GSM_TOT);

    // RoPE table
    {
        int total = S_LEN * (DH/2);
        rope_table_kernel<<<(total + 255) / 256, 256>>>(pos, csp, snp);
    }
    // Pre-split hs (hi+lo); all weights hi in one launch
    {
        int n4 = (MROWS * HID) / 4;
        cvt_split16_kernel<<<(n4 + 255) / 256, 256>>>(hs, hsh, hsl, n4);
        int nw = NQ4 + 2 * NK4 + NO4;
        cvt_hi16_w_kernel<<<(nw + 255) / 256, 256>>>(Wq, Wk, Wv, Wo,
                                                     wqh, wkh, wvh, woh);
    }
    // Fused Q/K/V projections (fp16 2-term, BK=32, R14 config)
    gemm_qkv_kernel<<<dim3(32, MROWS/128), 256, GSM_TOT>>>(
        hsh, hsl, wqh, wkh, wvh, qp, kp, vp);
    // Fused RoPE (q + k in one launch)
    {
        int tot = QTOT + KTOT;
        rope_apply_qk_kernel<<<(tot + 255) / 256, 256>>>(qp, kp, csp, snp);
    }
    // Attention (fp16 hi-only; fp16 hi/lo output)
    attn_mma_kernel<<<dim3(S_LEN/AQT, NH, BB), 256, ASM_TOT>>>(qp, kp, vp, aoh, aol);
    // Output projection (fp16 2-term, BK=32, R14 config)
    gemm_h_kernel<<<dim3(HID/128, MROWS/128), 256, GSM_TOT>>>(aoh, aol, woh, out, MROWS, HID, QCOLS);
}

// round 17
// speedup vs baseline: 1.6717x; 1.2524x over previous
#include <cuda_runtime.h>
#include <cuda_bf16.h>
#include <cuda_fp16.h>
#include <math.h>
#include <stdint.h>

// Problem constants
#define BB    2
#define S_LEN 2048
#define HID   2304
#define NH    8
#define NKVH  4
#define DH    256
#define MROWS (BB * S_LEN)        // 4096
#define QCOLS (NH * DH)           // 2048
#define KCOLS (NKVH * DH)         // 1024
#define WINDOW 1024
#define SCALING 0.0625f           // 256^-0.5
#define SOFTCAP 50.0f

// Scratch (static device globals; no runtime allocation allowed)
__device__ float g_q [(size_t)MROWS * QCOLS];   // 32 MB
__device__ float g_k [(size_t)MROWS * KCOLS];   // 16 MB
__device__ float g_v [(size_t)MROWS * KCOLS];   // 16 MB
__device__ float g_cos[S_LEN * (DH/2)];         // 1 MB
__device__ float g_sin[S_LEN * (DH/2)];         // 1 MB

// fp16 hi buffers (single-term GEMM operands)
__device__ __half g_hsh[(size_t)MROWS * HID];
__device__ __half g_wqh[(size_t)QCOLS * HID];
__device__ __half g_wkh[(size_t)KCOLS * HID];
__device__ __half g_wvh[(size_t)KCOLS * HID];
__device__ __half g_woh[(size_t)HID * QCOLS];
__device__ __half g_aoh[(size_t)MROWS * QCOLS];

// ============================================================================
// Helpers
// ============================================================================
__device__ __forceinline__ uint32_t smem_u32(const void* p) {
    uint32_t a;
    asm("{ .reg .u64 t; cvta.to.shared.u64 t, %1; cvt.u32.u64 %0, t; }"
        : "=r"(a) : "l"(p));
    return a;
}
__device__ __forceinline__ uint32_t pack_h2(__half a, __half b) {
    __half2 p = __halves2half2(a, b);
    return *reinterpret_cast<uint32_t*>(&p);
}
__device__ __forceinline__ void ldsm4(uint32_t* r, uint32_t addr) {
    asm volatile("ldmatrix.sync.aligned.m8n8.x4.shared.b16 {%0,%1,%2,%3}, [%4];"
                 : "=r"(r[0]), "=r"(r[1]), "=r"(r[2]), "=r"(r[3]) : "r"(addr));
}
__device__ __forceinline__ void ldsm4t(uint32_t* r, uint32_t addr) {
    asm volatile("ldmatrix.sync.aligned.m8n8.x4.trans.shared.b16 {%0,%1,%2,%3}, [%4];"
                 : "=r"(r[0]), "=r"(r[1]), "=r"(r[2]), "=r"(r[3]) : "r"(addr));
}
// fp16 mma
__device__ __forceinline__ void mma16816h(float* c, const uint32_t* a, const uint32_t* b) {
    asm volatile("mma.sync.aligned.m16n8k16.row.col.f32.f16.f16.f32 "
                 "{%0,%1,%2,%3}, {%4,%5,%6,%7}, {%8,%9}, {%0,%1,%2,%3};"
                 : "+f"(c[0]), "+f"(c[1]), "+f"(c[2]), "+f"(c[3])
                 : "r"(a[0]), "r"(a[1]), "r"(a[2]), "r"(a[3]),
                   "r"(b[0]), "r"(b[1]));
}
__device__ __forceinline__ void cp16(uint32_t dst, const void* src) {
    asm volatile("cp.async.ca.shared.global [%0], [%1], 16;"
                 :: "r"(dst), "l"(src) : "memory");
}
#define CP_COMMIT() asm volatile("cp.async.commit_group;" ::: "memory")
#define CP_WAIT0()  asm volatile("cp.async.wait_group 0;" ::: "memory")

// ---------------------------------------------------------------------------
// Fused fp32 -> fp16 hi for hs + all four weight matrices, one launch
// ---------------------------------------------------------------------------
#define NH4 ((MROWS * HID) / 4)
#define NQ4 ((QCOLS * HID) / 4)
#define NK4 ((KCOLS * HID) / 4)
#define NO4 ((HID * QCOLS) / 4)
__global__ void cvt_hi16_all_kernel(const float* __restrict__ hs,
                                    const float* __restrict__ Wq,
                                    const float* __restrict__ Wk,
                                    const float* __restrict__ Wv,
                                    const float* __restrict__ Wo,
                                    __half* __restrict__ hsh,
                                    __half* __restrict__ wqh, __half* __restrict__ wkh,
                                    __half* __restrict__ wvh, __half* __restrict__ woh) {
    int i = blockIdx.x * blockDim.x + threadIdx.x;
    const float* x;
    __half* y;
    if (i < NH4) { x = hs; y = hsh; }
    else if (i < NH4 + NQ4) { x = Wq; y = wqh; i -= NH4; }
    else if (i < NH4 + NQ4 + NK4) { x = Wk; y = wkh; i -= NH4 + NQ4; }
    else if (i < NH4 + NQ4 + 2 * NK4) { x = Wv; y = wvh; i -= NH4 + NQ4 + NK4; }
    else if (i < NH4 + NQ4 + 2 * NK4 + NO4) { x = Wo; y = woh; i -= NH4 + NQ4 + 2 * NK4; }
    else return;
    float4 a = ((const float4*)x)[i];
    ((uint2*)y)[i] = make_uint2(
        pack_h2(__float2half_rn(a.x), __float2half_rn(a.y)),
        pack_h2(__float2half_rn(a.z), __float2half_rn(a.w)));
}

// ---------------------------------------------------------------------------
// RoPE table
// ---------------------------------------------------------------------------
__global__ void rope_table_kernel(const int* __restrict__ pos,
                                  float* __restrict__ cs, float* __restrict__ sn) {
    int idx = blockIdx.x * blockDim.x + threadIdx.x;
    if (idx >= S_LEN * (DH/2)) return;
    int s = idx >> 7;
    int j = idx & 127;
    double invf = pow(10000.0, -(double)j / 128.0);
    float freq = (float)pos[s] * (float)invf;
    cs[idx] = cosf(freq);
    sn[idx] = sinf(freq);
}

// ---------------------------------------------------------------------------
// Fused RoPE apply for q (NH heads) and k (NKVH heads), one launch.
// ---------------------------------------------------------------------------
#define QTOT (MROWS * NH * 128)
#define KTOT (MROWS * NKVH * 128)
__global__ void rope_apply_qk_kernel(float* __restrict__ xq, float* __restrict__ xk,
                                     const float* __restrict__ cs,
                                     const float* __restrict__ sn) {
    int idx = blockIdx.x * blockDim.x + threadIdx.x;
    float* x;
    int nh;
    if (idx < QTOT) { x = xq; nh = NH; }
    else if (idx < QTOT + KTOT) { x = xk; nh = NKVH; idx -= QTOT; }
    else return;
    int per_row = nh * 128;
    int mrow = idx / per_row;
    int rp   = idx - mrow * per_row;
    int hh = rp >> 7;
    int j  = rp & 127;
    int s = mrow & (S_LEN - 1);
    float c  = cs[s * 128 + j];
    float sv = sn[s * 128 + j];
    size_t base = (size_t)mrow * (nh * 256) + hh * 256 + j;
    float x1 = x[base];
    float x2 = x[base + 128];
    x[base]       = x1 * c - x2 * sv;
    x[base + 128] = x2 * c + x1 * sv;
}

// ---------------------------------------------------------------------------
// Single-term fp16 GEMM core (NT): C = Ah Bh, fp32 accum.
// CTA tile 128x128, BK=32, 256 threads / 8 warps, warp grid 4m x 2n,
// warp tile 32x64. cp.async 2-stage, single sync per chunk. 2 CTA/SM.
// ---------------------------------------------------------------------------
#define GBK 32
#define ROWB 80
#define TILEB (128 * ROWB)         // 10240
#define STAGEB (2 * TILEB)         // 20480
#define GSM_TOT (2 * STAGEB)       // 40960

__device__ __forceinline__ void gemm_core(
    const __half* Ah, const __half* Bh,
    float* C, int m0, int n0, int N, int K, unsigned char* gsm)
{
    uint32_t sb = smem_u32(gsm);
    int tid  = threadIdx.x;
    int wid  = tid >> 5;
    int lane = tid & 31;
    int wm = (wid & 3) * 32;       // 4 m-warps
    int wn = (wid >> 2) * 64;      // 2 n-warps

    float acc[2][8][4];
#pragma unroll
    for (int i = 0; i < 2; i++)
#pragma unroll
        for (int j = 0; j < 8; j++)
#pragma unroll
            for (int t = 0; t < 4; t++) acc[i][j][t] = 0.f;

    // copy mapping: 2 threads per row; each covers 32 B (2 x cp16) per tile
    int lr   = tid >> 1;
    int sseg = (tid & 1) * 32;
    const char* pAh = (const char*)(Ah + (size_t)(m0 + lr) * K) + sseg;
    const char* pBh = (const char*)(Bh + (size_t)(n0 + lr) * K) + sseg;
    uint32_t dbase = sb + lr * ROWB + sseg;

    int alr = lane & 15;
    int akh = (lane >> 4) * 16;
    uint32_t aAh = sb + 0 * TILEB + (wm + alr) * ROWB + akh;
    int blr = (lane & 7) + ((lane >> 4) << 3);
    int bkh = ((lane >> 3) & 1) * 16;
    uint32_t aBh = sb + 1 * TILEB + (wn + blr) * ROWB + bkh;

    int nchunks = K / GBK;

    {
        uint32_t d = dbase;
        cp16(d + 0 * TILEB, pAh);  cp16(d + 0 * TILEB + 16, pAh + 16);
        cp16(d + 1 * TILEB, pBh);  cp16(d + 1 * TILEB + 16, pBh + 16);
        CP_COMMIT();
    }

#pragma unroll 1
    for (int ch = 0; ch < nchunks; ch++) {
        int st = ch & 1;
        CP_WAIT0();
        __syncthreads();
        if (ch + 1 < nchunks) {
            uint32_t d = dbase + (st ^ 1) * STAGEB;
            size_t go = (size_t)(ch + 1) * (GBK * 2);
            cp16(d + 0 * TILEB, pAh + go);  cp16(d + 0 * TILEB + 16, pAh + go + 16);
            cp16(d + 1 * TILEB, pBh + go);  cp16(d + 1 * TILEB + 16, pBh + go + 16);
        }
        CP_COMMIT();

        uint32_t so = st * STAGEB;
#pragma unroll
        for (int ks = 0; ks < 2; ks++) {
            uint32_t ah[2][4], bh[4][4];
#pragma unroll
            for (int mt = 0; mt < 2; mt++)
                ldsm4(ah[mt], aAh + so + mt * (16 * ROWB) + ks * 32);
#pragma unroll
            for (int p = 0; p < 4; p++)
                ldsm4(bh[p], aBh + so + p * (16 * ROWB) + ks * 32);
#pragma unroll
            for (int mt = 0; mt < 2; mt++) {
#pragma unroll
                for (int nt = 0; nt < 8; nt++) {
                    const uint32_t* bhp = &bh[nt >> 1][(nt & 1) * 2];
                    mma16816h(acc[mt][nt], ah[mt], bhp);
                }
            }
        }
    }

    int cr = lane >> 2;
    int cc = (lane & 3) * 2;
#pragma unroll
    for (int mt = 0; mt < 2; mt++) {
#pragma unroll
        for (int nt = 0; nt < 8; nt++) {
            int row = m0 + wm + mt * 16 + cr;
            int col = n0 + wn + nt * 8 + cc;
            *(float2*)(C + (size_t)row * N + col) =
                make_float2(acc[mt][nt][0], acc[mt][nt][1]);
            *(float2*)(C + (size_t)(row + 8) * N + col) =
                make_float2(acc[mt][nt][2], acc[mt][nt][3]);
        }
    }
}

__global__ __launch_bounds__(256) void gemm_qkv_kernel(
    const __half* __restrict__ Ah,
    const __half* __restrict__ Wqh, const __half* __restrict__ Wkh,
    const __half* __restrict__ Wvh,
    float* __restrict__ q, float* __restrict__ k, float* __restrict__ v)
{
    extern __shared__ unsigned char gsm[];
    int bx = blockIdx.x;
    int m0 = blockIdx.y * 128;
    const __half* Bh;
    float* C;
    int n0, N;
    if (bx < 16)      { Bh = Wqh; C = q; N = QCOLS; n0 = bx * 128; }
    else if (bx < 24) { Bh = Wkh; C = k; N = KCOLS; n0 = (bx - 16) * 128; }
    else              { Bh = Wvh; C = v; N = KCOLS; n0 = (bx - 24) * 128; }
    gemm_core(Ah, Bh, C, m0, n0, N, HID, gsm);
}

__global__ __launch_bounds__(256) void gemm_h_kernel(
    const __half* __restrict__ Ah, const __half* __restrict__ Bh,
    float* __restrict__ C, int M, int N, int K)
{
    extern __shared__ unsigned char gsm[];
    gemm_core(Ah, Bh, C, blockIdx.y * 128, blockIdx.x * 128, N, K, gsm);
}

// ---------------------------------------------------------------------------
// mma flash attention — fp16 hi-only (R15/R16 version); hi-only output.
// smem: QH (128 x 528) + KH + VH (16 x 528 each) = 84.5 KB.
// ---------------------------------------------------------------------------
#define AQT 128
#define ATK 16
#define QSTR 528
#define KSTR 528
#define ASM_QH 0
#define ASM_KH (AQT * QSTR)                 // 67584
#define ASM_VH (ASM_KH + ATK * KSTR)        // 76032
#define ASM_TOT (ASM_VH + ATK * KSTR)       // 84480

__global__ __launch_bounds__(256, 1) void attn_mma_kernel(
    const float* __restrict__ q, const float* __restrict__ k,
    const float* __restrict__ v,
    __half* __restrict__ oh)
{
    extern __shared__ char asmem[];
    uint32_t sb = smem_u32(asmem);
    int tid = threadIdx.x, wid = tid >> 5, lane = tid & 31;
    int qt = blockIdx.x, h = blockIdx.y, b = blockIdx.z;
    int kvh = h >> 1;
    int q0 = qt * AQT;

    // --- Load + convert Q tile into smem fp16 hi (once) ---
    {
        int row = tid >> 1;
        int c0  = (tid & 1) * 128;
        const float* qrow = q + (size_t)(b * S_LEN + q0 + row) * QCOLS + h * DH + c0;
        char* dh = asmem + ASM_QH + row * QSTR + c0 * 2;
#pragma unroll
        for (int i = 0; i < 32; i++) {
            float4 a = *(const float4*)(qrow + i * 4);
            *(uint2*)(dh + i * 8) = make_uint2(
                pack_h2(__float2half_rn(a.x), __float2half_rn(a.y)),
                pack_h2(__float2half_rn(a.z), __float2half_rn(a.w)));
        }
    }

    int kstart = q0 - (WINDOW - 1);
    if (kstart < 0) kstart = 0;
    kstart &= ~(ATK - 1);
    int ntiles = (q0 + AQT - 1 - kstart) / ATK + 1;

    int prow = tid >> 4;
    int pcol = (tid & 15) * 16;
    const float* kbase = k + (size_t)(b * S_LEN) * KCOLS + kvh * DH;
    const float* vbase = v + (size_t)(b * S_LEN) * KCOLS + kvh * DH;

    float4 pk[4], pv[4];
    {
        const float* kr = kbase + (size_t)(kstart + prow) * KCOLS + pcol;
        const float* vr = vbase + (size_t)(kstart + prow) * KCOLS + pcol;
#pragma unroll
        for (int i = 0; i < 4; i++) { pk[i] = *(const float4*)(kr + i * 4);
                                      pv[i] = *(const float4*)(vr + i * 4); }
    }

    uint32_t aQh = sb + ASM_QH + (wid * 16 + (lane & 15)) * QSTR + (lane >> 4) * 16;
    uint32_t aKh = sb + ASM_KH + ((lane & 7) + ((lane >> 4) << 3)) * KSTR + ((lane >> 3) & 1) * 16;
    uint32_t aVh = sb + ASM_VH + ((lane & 7) + (((lane >> 3) & 1) << 3)) * KSTR + (lane >> 4) * 16;

    float mrow0 = -1e30f, mrow1 = -1e30f;
    float lrow0 = 0.f, lrow1 = 0.f;
    float oacc[32][4];
#pragma unroll
    for (int i = 0; i < 32; i++)
#pragma unroll
        for (int t = 0; t < 4; t++) oacc[i][t] = 0.f;

    int r0 = q0 + wid * 16 + (lane >> 2);

#pragma unroll 1
    for (int t = 0; t < ntiles; t++) {
        __syncthreads();
        {
            char* kh = asmem + ASM_KH + prow * KSTR + pcol * 2;
            char* vh = asmem + ASM_VH + prow * KSTR + pcol * 2;
#pragma unroll
            for (int i = 0; i < 4; i++) {
                float4 a = pk[i];
                *(uint2*)(kh + i * 8) = make_uint2(
                    pack_h2(__float2half_rn(a.x), __float2half_rn(a.y)),
                    pack_h2(__float2half_rn(a.z), __float2half_rn(a.w)));
                float4 bv = pv[i];
                *(uint2*)(vh + i * 8) = make_uint2(
                    pack_h2(__float2half_rn(bv.x), __float2half_rn(bv.y)),
                    pack_h2(__float2half_rn(bv.z), __float2half_rn(bv.w)));
            }
        }
        __syncthreads();
        if (t + 1 < ntiles) {
            int kt = kstart + (t + 1) * ATK;
            const float* kr = kbase + (size_t)(kt + prow) * KCOLS + pcol;
            const float* vr = vbase + (size_t)(kt + prow) * KCOLS + pcol;
#pragma unroll
            for (int i = 0; i < 4; i++) { pk[i] = *(const float4*)(kr + i * 4);
                                          pv[i] = *(const float4*)(vr + i * 4); }
        }

        int key0 = kstart + t * ATK;
        // ---- scores: Qh Kh ----
        float sc[2][4];
#pragma unroll
        for (int nt = 0; nt < 2; nt++)
#pragma unroll
            for (int e = 0; e < 4; e++) sc[nt][e] = 0.f;
#pragma unroll
        for (int dc = 0; dc < 16; dc++) {
            uint32_t qh[4], kh4[4];
            ldsm4(qh,  aQh + dc * 32);
            ldsm4(kh4, aKh + dc * 32);
#pragma unroll
            for (int nt = 0; nt < 2; nt++)
                mma16816h(sc[nt], qh, &kh4[nt * 2]);
        }
        // ---- softcap + mask ----
#pragma unroll
        for (int nt = 0; nt < 2; nt++) {
#pragma unroll
            for (int e = 0; e < 4; e++) {
                int row = r0 + (e >> 1) * 8;
                int col = key0 + nt * 8 + (lane & 3) * 2 + (e & 1);
                float u = sc[nt][e] * (SCALING / SOFTCAP);
                float eu = __expf(-2.f * fabsf(u));
                float th = __fdividef(1.f - eu, 1.f + eu);
                float s = copysignf(th, u) * SOFTCAP;
                bool ok = (col <= row) && (row - col < WINDOW);
                sc[nt][e] = ok ? s : -3.0e38f;
            }
        }
        // ---- online softmax ----
        float tm0 = fmaxf(fmaxf(sc[0][0], sc[0][1]), fmaxf(sc[1][0], sc[1][1]));
        float tm1 = fmaxf(fmaxf(sc[0][2], sc[0][3]), fmaxf(sc[1][2], sc[1][3]));
        tm0 = fmaxf(tm0, __shfl_xor_sync(0xffffffffu, tm0, 1));
        tm0 = fmaxf(tm0, __shfl_xor_sync(0xffffffffu, tm0, 2));
        tm1 = fmaxf(tm1, __shfl_xor_sync(0xffffffffu, tm1, 1));
        tm1 = fmaxf(tm1, __shfl_xor_sync(0xffffffffu, tm1, 2));
        float mnew0 = fmaxf(mrow0, tm0);
        float mnew1 = fmaxf(mrow1, tm1);
        float al0 = __expf(mrow0 - mnew0);
        float al1 = __expf(mrow1 - mnew1);
        mrow0 = mnew0; mrow1 = mnew1;
#pragma unroll
        for (int nt = 0; nt < 2; nt++) {
            sc[nt][0] = __expf(sc[nt][0] - mnew0);
            sc[nt][1] = __expf(sc[nt][1] - mnew0);
            sc[nt][2] = __expf(sc[nt][2] - mnew1);
            sc[nt][3] = __expf(sc[nt][3] - mnew1);
        }
        float rs0 = sc[0][0] + sc[0][1] + sc[1][0] + sc[1][1];
        float rs1 = sc[0][2] + sc[0][3] + sc[1][2] + sc[1][3];
        rs0 += __shfl_xor_sync(0xffffffffu, rs0, 1);
        rs0 += __shfl_xor_sync(0xffffffffu, rs0, 2);
        rs1 += __shfl_xor_sync(0xffffffffu, rs1, 1);
        rs1 += __shfl_xor_sync(0xffffffffu, rs1, 2);
        lrow0 = lrow0 * al0 + rs0;
        lrow1 = lrow1 * al1 + rs1;
        if (!__all_sync(0xffffffffu, (al0 == 1.f) & (al1 == 1.f))) {
#pragma unroll
            for (int i = 0; i < 32; i++) {
                oacc[i][0] *= al0; oacc[i][1] *= al0;
                oacc[i][2] *= al1; oacc[i][3] *= al1;
            }
        }
        // ---- P fragments fp16 hi + PV ----
        uint32_t pa[4];
        pa[0] = pack_h2(__float2half_rn(sc[0][0]), __float2half_rn(sc[0][1]));
        pa[1] = pack_h2(__float2half_rn(sc[0][2]), __float2half_rn(sc[0][3]));
        pa[2] = pack_h2(__float2half_rn(sc[1][0]), __float2half_rn(sc[1][1]));
        pa[3] = pack_h2(__float2half_rn(sc[1][2]), __float2half_rn(sc[1][3]));
#pragma unroll
        for (int g = 0; g < 16; g++) {
            uint32_t vbh[4];
            ldsm4t(vbh, aVh + g * 32);
            mma16816h(oacc[2 * g],     pa, &vbh[0]);
            mma16816h(oacc[2 * g + 1], pa, &vbh[2]);
        }
    }

    // ---- epilogue: write fp16 hi directly ----
    float inv0 = __fdividef(1.f, lrow0);
    float inv1 = __fdividef(1.f, lrow1);
    size_t off0 = (size_t)(b * S_LEN + r0) * QCOLS + h * DH;
    size_t off1 = off0 + (size_t)8 * QCOLS;
#pragma unroll
    for (int i = 0; i < 32; i++) {
        int col = i * 8 + (lane & 3) * 2;
        *(uint32_t*)(oh + off0 + col) =
            pack_h2(__float2half_rn(oacc[i][0] * inv0),
                    __float2half_rn(oacc[i][1] * inv0));
        *(uint32_t*)(oh + off1 + col) =
            pack_h2(__float2half_rn(oacc[i][2] * inv1),
                    __float2half_rn(oacc[i][3] * inv1));
    }
}

// ---------------------------------------------------------------------------
// Launch
// ---------------------------------------------------------------------------
extern "C" void kernel_launch(void* const* d_in, const int* in_sizes, int n_in,
                              void* d_out, int out_size) {
    const float* hs  = (const float*)d_in[0];
    const float* Wq  = (const float*)d_in[1];
    const float* Wk  = (const float*)d_in[2];
    const float* Wv  = (const float*)d_in[3];
    const float* Wo  = (const float*)d_in[4];
    const int*   pos = (const int*)d_in[5];
    float* out = (float*)d_out;

    float *qp, *kp, *vp, *csp, *snp;
    cudaGetSymbolAddress((void**)&qp,  g_q);
    cudaGetSymbolAddress((void**)&kp,  g_k);
    cudaGetSymbolAddress((void**)&vp,  g_v);
    cudaGetSymbolAddress((void**)&csp, g_cos);
    cudaGetSymbolAddress((void**)&snp, g_sin);
    __half *hsh, *wqh, *wkh, *wvh, *woh, *aoh;
    cudaGetSymbolAddress((void**)&hsh, g_hsh);
    cudaGetSymbolAddress((void**)&wqh, g_wqh);
    cudaGetSymbolAddress((void**)&wkh, g_wkh);
    cudaGetSymbolAddress((void**)&wvh, g_wvh);
    cudaGetSymbolAddress((void**)&woh, g_woh);
    cudaGetSymbolAddress((void**)&aoh, g_aoh);

    cudaFuncSetAttribute(attn_mma_kernel,
                         cudaFuncAttributeMaxDynamicSharedMemorySize, ASM_TOT);
    cudaFuncSetAttribute(gemm_h_kernel,
                         cudaFuncAttributeMaxDynamicSharedMemorySize, GSM_TOT);
    cudaFuncSetAttribute(gemm_qkv_kernel,
                         cudaFuncAttributeMaxDynamicSharedMemorySize, GSM_TOT);

    // RoPE table
    {
        int total = S_LEN * (DH/2);
        rope_table_kernel<<<(total + 255) / 256, 256>>>(pos, csp, snp);
    }
    // hs + all weights -> fp16 hi, one launch
    {
        int nall = NH4 + NQ4 + 2 * NK4 + NO4;
        cvt_hi16_all_kernel<<<(nall + 255) / 256, 256>>>(hs, Wq, Wk, Wv, Wo,
                                                         hsh, wqh, wkh, wvh, woh);
    }
    // Fused Q/K/V projections (single-term fp16)
    gemm_qkv_kernel<<<dim3(32, MROWS/128), 256, GSM_TOT>>>(
        hsh, wqh, wkh, wvh, qp, kp, vp);
    // Fused RoPE (q + k in one launch)
    {
        int tot = QTOT + KTOT;
        rope_apply_qk_kernel<<<(tot + 255) / 256, 256>>>(qp, kp, csp, snp);
    }
    // Attention (fp16 hi-only; hi-only output)
    attn_mma_kernel<<<dim3(S_LEN/AQT, NH, BB), 256, ASM_TOT>>>(qp, kp, vp, aoh);
    // Output projection (single-term fp16)
    gemm_h_kernel<<<dim3(HID/128, MROWS/128), 256, GSM_TOT>>>(aoh, woh, out, MROWS, HID, QCOLS);
}